// round 1
// baseline (speedup 1.0000x reference)
#include <cuda_runtime.h>
#include <cuda_bf16.h>

// Problem constants
#define BB   4
#define CC_T 256     // total channels
#define HH   256
#define WW   256
#define MM   100
#define PP   7
#define NBINS 49     // P*P
#define CCK  32      // channels per chunk
#define NCHUNK (CC_T / CCK)   // 8
#define PMAX 17      // max patch side (analytic bound: <=16)
#define PITCHMAX (PMAX*PMAX + 1)  // 290

__global__ __launch_bounds__(256)
void roialign_kernel(const float* __restrict__ feature,
                     const float* __restrict__ boxes,
                     float* __restrict__ out)
{
    __shared__ float patch[CCK * PITCHMAX];   // ~37 KB, layout [c][pix]

    const int chunk = blockIdx.x;      // 0..7
    const int bm    = blockIdx.y;      // 0..399
    const int b     = bm / MM;

    // ---- box params (computed redundantly by all threads; cheap, cached) ----
    const float* box = boxes + bm * 7;
    const float bx0 = box[0];
    const float bx1 = box[1];
    const float bw  = box[5];
    const float bh  = box[4];
    const float bth = box[6];

    const float gw = (140.8f - (-140.8f)) / 256.0f;   // 1.1
    const float gh = (40.0f  - (-40.0f))  / 256.0f;   // 0.3125

    const float cx = (bx0 - (-140.8f)) / gw - 0.5f;
    const float cy = (bx1 - (-40.0f))  / gh - 0.5f;
    const float rw = bw / gw;                          // ENLARGE = 1
    const float rh = bh / gh;
    const float theta = -bth;
    const float cosv = cosf(theta);
    const float sinv = sinf(theta);
    const float bin_w = rw / (float)PP;
    const float bin_h = rh / (float)PP;

    // ---- analytic patch bounds (samples lie within +-(3.25/7)*(...) of center) ----
    const float extc = 3.25f / 7.0f;
    const float ac = fabsf(cosv), as = fabsf(sinv);
    const float ex = extc * (rw * ac + rh * as);
    const float ey = extc * (rh * ac + rw * as);

    int x0p = max(0, (int)floorf(cx - ex) - 1);
    int x1p = min(WW - 1, (int)floorf(cx + ex) + 2);
    int y0p = max(0, (int)floorf(cy - ey) - 1);
    int y1p = min(HH - 1, (int)floorf(cy + ey) + 2);
    int PW = x1p - x0p + 1;
    int PH = y1p - y0p + 1;
    if (PW > PMAX) { PW = PMAX; }
    if (PH > PMAX) { PH = PMAX; }
    if (PW < 1) PW = 1;
    if (PH < 1) PH = 1;

    const int NP    = PH * PW;
    const int pitch = NP | 1;            // odd pitch -> conflict-free [c][pix] access
    const int c0    = chunk * CCK;

    // ---- stage patch: global NCHW -> shared [c][pix], x innermost (coalesced) ----
    const float* fbase = feature + ((size_t)b * CC_T + c0) * (HH * WW);
    const int total = NP * CCK;
    for (int idx = threadIdx.x; idx < total; idx += 256) {
        int c   = idx / NP;
        int pix = idx - c * NP;
        int py  = pix / PW;
        int px  = pix - py * PW;
        patch[c * pitch + pix] =
            fbase[(size_t)c * (HH * WW) + (size_t)(y0p + py) * WW + (x0p + px)];
    }
    __syncthreads();

    // ---- compute: warp per bin (strided), lane = channel within chunk ----
    const int warp = threadIdx.x >> 5;
    const int lane = threadIdx.x & 31;
    const float* pr = patch + lane * pitch;

    for (int bin = warp; bin < NBINS; bin += 8) {
        const int py = bin / PP;
        const int px = bin - py * PP;
        float acc = 0.0f;

        #pragma unroll
        for (int s = 0; s < 4; s++) {
            const int sy = s >> 1, sx = s & 1;
            const float swy = sy ? 0.75f : 0.25f;
            const float swx = sx ? 0.75f : 0.25f;

            const float Yv = -rh * 0.5f + bin_h * ((float)py + swy);
            const float Xv = -rw * 0.5f + bin_w * ((float)px + swx);
            const float ysf = Yv * cosv - Xv * sinv + cy;
            const float xsf = Yv * sinv + Xv * cosv + cx;

            const bool valid = (ysf > -1.0f) && (ysf < (float)HH) &&
                               (xsf > -1.0f) && (xsf < (float)WW);

            float y = fmaxf(ysf, 0.0f);
            float x = fmaxf(xsf, 0.0f);
            int y0 = min((int)floorf(y), HH - 1);
            int x0 = min((int)floorf(x), WW - 1);
            int y1 = min(y0 + 1, HH - 1);
            int x1 = min(x0 + 1, WW - 1);
            float ly = (y0 >= HH - 1) ? 0.0f : (y - (float)y0);
            float lx = (x0 >= WW - 1) ? 0.0f : (x - (float)x0);
            float hy = 1.0f - ly;
            float hx = 1.0f - lx;

            // patch-relative cells (defensively clamped; in-bounds by construction)
            int ry0 = min(max(y0 - y0p, 0), PH - 1);
            int ry1 = min(max(y1 - y0p, 0), PH - 1);
            int rx0 = min(max(x0 - x0p, 0), PW - 1);
            int rx1 = min(max(x1 - x0p, 0), PW - 1);

            float v00 = pr[ry0 * PW + rx0];
            float v01 = pr[ry0 * PW + rx1];
            float v10 = pr[ry1 * PW + rx0];
            float v11 = pr[ry1 * PW + rx1];

            float samp = hy * hx * v00 + hy * lx * v01 + ly * hx * v10 + ly * lx * v11;
            acc += valid ? samp : 0.0f;
        }

        // out layout: (bm, py, px, c) == (bm*49 + bin)*256 + c
        out[((size_t)bm * NBINS + bin) * CC_T + c0 + lane] = acc * 0.25f;
    }
}

extern "C" void kernel_launch(void* const* d_in, const int* in_sizes, int n_in,
                              void* d_out, int out_size) {
    const float* feature = (const float*)d_in[0];
    const float* boxes   = (const float*)d_in[1];
    // d_in[2] = mask, unused (all ones / does not affect pooled output)
    float* out = (float*)d_out;

    dim3 grid(NCHUNK, BB * MM);   // (8, 400)
    roialign_kernel<<<grid, 256>>>(feature, boxes, out);
}

// round 4
// speedup vs baseline: 1.5885x; 1.5885x over previous
#include <cuda_runtime.h>
#include <cuda_bf16.h>

// Problem constants
#define BB   4
#define CC_T 256     // total channels
#define HH   256
#define WW   256
#define MM   100
#define PP   7
#define NBINS 49     // P*P
#define NSAMP (NBINS * 4)       // 196 (bin, sample) pairs
#define CCK  32      // channels per chunk
#define NCHUNK (CC_T / CCK)     // 8
#define PMAX 17      // max patch side (analytic bound: <=16)
#define PITCHMAX (PMAX*PMAX + 1)  // 290

__global__ __launch_bounds__(256)
void roialign_kernel(const float* __restrict__ feature,
                     const float* __restrict__ boxes,
                     float* __restrict__ out)
{
    __shared__ float  patch[CCK * PITCHMAX];   // ~37.1 KB, layout [c][pix]
    __shared__ int4   s_cells[NSAMP];          // 3136 B: 4 patch cell offsets per sample
    __shared__ float4 s_wts[NSAMP];            // 3136 B: 4 weights (valid & 0.25 folded)

    const int tid   = threadIdx.x;
    const int chunk = blockIdx.x;      // 0..7
    const int bm    = blockIdx.y;      // 0..399
    const int b     = bm / MM;

    // ---- box params (computed redundantly by all threads) ----
    const float* box = boxes + bm * 7;
    const float bx0 = box[0];
    const float bx1 = box[1];
    const float bw  = box[5];
    const float bh  = box[4];
    const float bth = box[6];

    const float gw = 281.6f / 256.0f;   // 1.1
    const float gh = 80.0f  / 256.0f;   // 0.3125

    const float cx = (bx0 + 140.8f) / gw - 0.5f;
    const float cy = (bx1 + 40.0f)  / gh - 0.5f;
    const float rw = bw / gw;           // ENLARGE = 1
    const float rh = bh / gh;
    const float theta = -bth;
    const float cosv = cosf(theta);
    const float sinv = sinf(theta);
    const float bin_w = rw * (1.0f / (float)PP);
    const float bin_h = rh * (1.0f / (float)PP);

    // ---- analytic patch bounds (samples within +-(3.25/7)*(...) of center) ----
    const float extc = 3.25f / 7.0f;
    const float ac = fabsf(cosv), as = fabsf(sinv);
    const float ex = extc * (rw * ac + rh * as);
    const float ey = extc * (rh * ac + rw * as);

    int x0p = max(0, (int)floorf(cx - ex) - 1);
    int x1p = min(WW - 1, (int)floorf(cx + ex) + 2);
    int y0p = max(0, (int)floorf(cy - ey) - 1);
    int y1p = min(HH - 1, (int)floorf(cy + ey) + 2);
    int PW = x1p - x0p + 1;
    int PH = y1p - y0p + 1;
    if (PW > PMAX) PW = PMAX;
    if (PH > PMAX) PH = PMAX;
    if (PW < 1) PW = 1;
    if (PH < 1) PH = 1;

    const int NP    = PH * PW;
    const int pitch = NP | 1;            // odd pitch -> conflict-free [c][pix]
    const int c0    = chunk * CCK;

    // ---- phase A: precompute per-(bin,sample) tap cells + weights (196 thr) ----
    if (tid < NSAMP) {
        const int bin = tid >> 2;
        const int s   = tid & 3;
        const int py  = bin / PP;              // constant divisor -> magic mul
        const int px  = bin - py * PP;
        const float swy = (s & 2) ? 0.75f : 0.25f;
        const float swx = (s & 1) ? 0.75f : 0.25f;

        const float Yv = -rh * 0.5f + bin_h * ((float)py + swy);
        const float Xv = -rw * 0.5f + bin_w * ((float)px + swx);
        const float ysf = Yv * cosv - Xv * sinv + cy;
        const float xsf = Yv * sinv + Xv * cosv + cx;

        const bool valid = (ysf > -1.0f) && (ysf < (float)HH) &&
                           (xsf > -1.0f) && (xsf < (float)WW);

        float y = fmaxf(ysf, 0.0f);
        float x = fmaxf(xsf, 0.0f);
        int y0 = min((int)floorf(y), HH - 1);
        int x0 = min((int)floorf(x), WW - 1);
        int y1 = min(y0 + 1, HH - 1);
        int x1 = min(x0 + 1, WW - 1);
        float ly = (y0 >= HH - 1) ? 0.0f : (y - (float)y0);
        float lx = (x0 >= WW - 1) ? 0.0f : (x - (float)x0);
        float hy = 1.0f - ly;
        float hx = 1.0f - lx;

        // patch-relative cells (in-bounds by construction; defensive clamp)
        int ry0 = min(max(y0 - y0p, 0), PH - 1);
        int ry1 = min(max(y1 - y0p, 0), PH - 1);
        int rx0 = min(max(x0 - x0p, 0), PW - 1);
        int rx1 = min(max(x1 - x0p, 0), PW - 1);

        const float sc = valid ? 0.25f : 0.0f;   // fold validity + mean(2x2)
        s_cells[tid] = make_int4(ry0 * PW + rx0, ry0 * PW + rx1,
                                 ry1 * PW + rx0, ry1 * PW + rx1);
        s_wts[tid]   = make_float4(hy * hx * sc, hy * lx * sc,
                                   ly * hx * sc, ly * lx * sc);
    }

    // ---- phase B: stage patch NCHW -> shared [c][pix]; division-free ----
    const int warp = tid >> 5;
    const int lane = tid & 31;
    {
        const float* fbase = feature + ((size_t)b * CC_T + c0) * (HH * WW)
                           + (size_t)y0p * WW + x0p;
        for (int c = warp; c < CCK; c += 8) {          // 4 channels per warp
            const float* g = fbase + (size_t)c * (HH * WW);
            float* sp = patch + c * pitch;
            if (lane < PW) {
                int goff = lane;
                int soff = lane;
                for (int py = 0; py < PH; py++) {
                    sp[soff] = g[goff];
                    goff += WW;
                    soff += PW;
                }
            }
        }
    }
    __syncthreads();

    // ---- phase C: warp per bin (strided), lane = channel ----
    const float* pr = patch + lane * pitch;
    float* obase = out + (size_t)bm * (NBINS * CC_T) + c0 + lane;

    for (int bin = warp; bin < NBINS; bin += 8) {
        float acc = 0.0f;
        #pragma unroll
        for (int s = 0; s < 4; s++) {
            const int4   cl = s_cells[bin * 4 + s];   // broadcast LDS.128
            const float4 w  = s_wts[bin * 4 + s];     // broadcast LDS.128
            acc += w.x * pr[cl.x];
            acc += w.y * pr[cl.y];
            acc += w.z * pr[cl.z];
            acc += w.w * pr[cl.w];
        }
        obase[(size_t)bin * CC_T] = acc;
    }
}

extern "C" void kernel_launch(void* const* d_in, const int* in_sizes, int n_in,
                              void* d_out, int out_size) {
    const float* feature = (const float*)d_in[0];
    const float* boxes   = (const float*)d_in[1];
    // d_in[2] = mask, unused (all ones; does not affect pooled output)
    float* out = (float*)d_out;

    dim3 grid(NCHUNK, BB * MM);   // (8, 400)
    roialign_kernel<<<grid, 256>>>(feature, boxes, out);
}